// round 8
// baseline (speedup 1.0000x reference)
#include <cuda_runtime.h>
#include <cuda_fp16.h>
#include <math.h>
#include <stdint.h>

#define H   128
#define H2  256
#define H3  384
#define H6  768
#define WMC 257          // W_msg columns = 2H+1

#define MAXN 50000
#define MAXE 800000
#define MAXT 4
#define MAXNB ((MAXN + 1023) / 1024)

// ---------------- scratch (static device globals; no allocation) ----------------
__device__ float g_S   [(size_t)MAXN * H];    // gathered sum of hv[src] into dst
__device__ float g_Y   [(size_t)MAXN * H6];   // hv @ [Wc_d ; W_hh]^T
__device__ float g_Ys  [(size_t)MAXN * H3];   // S @ Wc_s^T
__device__ float g_h0  [(size_t)MAXN * H];
__device__ float g_h1  [(size_t)MAXN * H];
__device__ float g_deg [MAXN];
__device__ float g_se  [MAXN];
__device__ float g_Wbig[(size_t)MAXT * H6 * H];  // [Wc_d ; W_hh], 768x128 per round
__device__ float g_Wcs [(size_t)MAXT * H3 * H];  // Wc_s, 384x128 per round
__device__ float g_u1  [MAXT * H3];              // W_ih @ w_e
__device__ float g_u2  [MAXT * H3];              // W_ih @ b_msg
__device__ int   g_off [MAXN + 1];               // CSR offsets (by dst)
__device__ int   g_cur [MAXN];                   // fill cursors
__device__ int   g_csrc[MAXE];                   // CSR src lists
__device__ int   g_bsum[MAXNB];                  // scan partials
__device__ int   g_bpre[MAXNB];

// ---------------- utility ----------------
__global__ void zero2_kernel(float* __restrict__ p, float* __restrict__ q, int n) {
    int i = blockIdx.x * blockDim.x + threadIdx.x;
    int stride = gridDim.x * blockDim.x;
    for (int k = i; k < n; k += stride) { p[k] = 0.f; q[k] = 0.f; }
}

__global__ void degse_kernel(const int* __restrict__ dst, const float* __restrict__ he, int E) {
    int e = blockIdx.x * blockDim.x + threadIdx.x;
    if (e >= E) return;
    int d = dst[e];
    atomicAdd(&g_deg[d], 1.0f);
    atomicAdd(&g_se[d], he[e]);
}

// ---------------- CSR prefix scan: multi-block ----------------
__global__ void scan1_kernel(int N) {
    __shared__ int wsum[32];
    int i = blockIdx.x * 1024 + threadIdx.x;
    int lane = threadIdx.x & 31, wid = threadIdx.x >> 5;
    int v = (i < N) ? (int)g_deg[i] : 0;
    int x = v;
    #pragma unroll
    for (int o = 1; o < 32; o <<= 1) {
        int t = __shfl_up_sync(0xFFFFFFFFu, x, o);
        if (lane >= o) x += t;
    }
    if (lane == 31) wsum[wid] = x;
    __syncthreads();
    if (wid == 0) {
        int s = wsum[lane];
        #pragma unroll
        for (int o = 1; o < 32; o <<= 1) {
            int t = __shfl_up_sync(0xFFFFFFFFu, s, o);
            if (lane >= o) s += t;
        }
        wsum[lane] = s;
    }
    __syncthreads();
    int wpre = (wid == 0) ? 0 : wsum[wid - 1];
    if (i < N) g_off[i] = wpre + x - v;
    if (threadIdx.x == 1023) g_bsum[blockIdx.x] = wpre + x;
}

__global__ void scan2_kernel(int nb) {
    if (threadIdx.x == 0) {
        int s = 0;
        for (int b = 0; b < nb; b++) { int t = g_bsum[b]; g_bpre[b] = s; s += t; }
    }
}

__global__ void scan3_kernel(int N, int E) {
    int i = blockIdx.x * 1024 + threadIdx.x;
    if (i < N) {
        int o = g_off[i] + g_bpre[blockIdx.x];
        g_off[i] = o;
        g_cur[i] = o;
    }
    if (i == 0) g_off[N] = E;
}

__global__ void fill_kernel(const int* __restrict__ src, const int* __restrict__ dst, int E) {
    int e = blockIdx.x * blockDim.x + threadIdx.x;
    if (e >= E) return;
    int pos = atomicAdd(&g_cur[dst[e]], 1);
    g_csrc[pos] = src[e];
}

// ---------------- weight folding ----------------
// Wc[j][k] = sum_i W_ih[t][j][i] * W_msg[t][i][k]
// k <  H : -> g_Wbig rows 0..383 (Wc_d)
// k >= H : -> g_Wcs (Wc_s), col k-H
__global__ void fold_wc_kernel(const float* __restrict__ W_ih, const float* __restrict__ W_msg, int T) {
    long idx = (long)blockIdx.x * blockDim.x + threadIdx.x;
    if (idx >= (long)T * H3 * H2) return;
    int k = (int)(idx % H2);
    int j = (int)((idx / H2) % H3);
    int t = (int)(idx / ((long)H2 * H3));
    const float* wi = W_ih + ((size_t)t * H3 + j) * H2;
    const float* wm = W_msg + (size_t)t * H2 * WMC + k;
    float a0 = 0.f, a1 = 0.f, a2 = 0.f, a3 = 0.f;
    #pragma unroll 2
    for (int i = 0; i < H2; i += 4) {
        a0 += __ldg(wi + i)     * __ldg(wm + (size_t)(i)     * WMC);
        a1 += __ldg(wi + i + 1) * __ldg(wm + (size_t)(i + 1) * WMC);
        a2 += __ldg(wi + i + 2) * __ldg(wm + (size_t)(i + 2) * WMC);
        a3 += __ldg(wi + i + 3) * __ldg(wm + (size_t)(i + 3) * WMC);
    }
    float r = (a0 + a1) + (a2 + a3);
    if (k < H) g_Wbig[(size_t)t * H6 * H + (size_t)j * H + k] = r;
    else       g_Wcs [(size_t)t * H3 * H + (size_t)j * H + (k - H)] = r;
}

// copy W_hh into g_Wbig rows 384..767
__global__ void copy_whh_kernel(const float* __restrict__ W_hh, int T) {
    int i = blockIdx.x * blockDim.x + threadIdx.x;   // float4 index
    int total = T * H3 * H / 4;
    if (i >= total) return;
    int t = i / (H3 * H / 4);
    int r = i % (H3 * H / 4);
    const float4* srcp = (const float4*)(W_hh + (size_t)t * H3 * H) + r;
    float4* dstp = (float4*)(g_Wbig + (size_t)t * H6 * H + (size_t)H3 * H) + r;
    *dstp = *srcp;
}

__global__ void fold_u_kernel(const float* __restrict__ W_ih, const float* __restrict__ W_msg,
                              const float* __restrict__ b_msg, int T) {
    int idx = blockIdx.x * blockDim.x + threadIdx.x;
    if (idx >= T * H3) return;
    int j = idx % H3, t = idx / H3;
    const float* wi = W_ih + ((size_t)t * H3 + j) * H2;
    const float* wm = W_msg + (size_t)t * H2 * WMC;
    const float* bm = b_msg + (size_t)t * H2;
    float a1 = 0.f, a2 = 0.f;
    for (int i = 0; i < H2; i++) {
        float w = wi[i];
        a1 += w * wm[(size_t)i * WMC + H2];
        a2 += w * bm[i];
    }
    g_u1[idx] = a1;
    g_u2[idx] = a2;
}

// ---------------- gather: S[n] = sum_{e in CSR[n]} hv[csrc[e]], one warp/node ----
__global__ void gatherx_kernel(const float* __restrict__ hv, int N) {
    int n = (blockIdx.x * blockDim.x + threadIdx.x) >> 5;
    int lane = threadIdx.x & 31;
    if (n >= N) return;
    int beg = g_off[n], end = g_off[n + 1];
    float4 acc0 = make_float4(0.f, 0.f, 0.f, 0.f);
    float4 acc1 = make_float4(0.f, 0.f, 0.f, 0.f);
    int e = beg;
    for (; e + 2 <= end; e += 2) {
        int s0 = __ldg(g_csrc + e);
        int s1 = __ldg(g_csrc + e + 1);
        float4 v0 = *(((const float4*)(hv + (size_t)s0 * H)) + lane);
        float4 v1 = *(((const float4*)(hv + (size_t)s1 * H)) + lane);
        acc0.x += v0.x; acc0.y += v0.y; acc0.z += v0.z; acc0.w += v0.w;
        acc1.x += v1.x; acc1.y += v1.y; acc1.z += v1.z; acc1.w += v1.w;
    }
    if (e < end) {
        int s0 = __ldg(g_csrc + e);
        float4 v0 = *(((const float4*)(hv + (size_t)s0 * H)) + lane);
        acc0.x += v0.x; acc0.y += v0.y; acc0.z += v0.z; acc0.w += v0.w;
    }
    acc0.x += acc1.x; acc0.y += acc1.y; acc0.z += acc1.z; acc0.w += acc1.w;
    ((float4*)(g_S + (size_t)n * H))[lane] = acc0;
}

// ---------------- 3xFP16 tensor-core GEMM (NT): C = A @ B^T, fp32-accurate ---------
#define SMS 136

__device__ __forceinline__ void split_h2(float x, float y, uint32_t& hi, uint32_t& lo) {
    __half hx = __float2half_rn(x);
    __half hy = __float2half_rn(y);
    __half lx = __float2half_rn(x - __half2float(hx));
    __half ly = __float2half_rn(y - __half2float(hy));
    __half2 h = __halves2half2(hx, hy);
    __half2 l = __halves2half2(lx, ly);
    hi = *(uint32_t*)&h;
    lo = *(uint32_t*)&l;
}

__device__ __forceinline__ void mma_f16(float* acc, const uint32_t* a, const uint32_t* b) {
    asm volatile(
        "mma.sync.aligned.m16n8k16.row.col.f32.f16.f16.f32 "
        "{%0,%1,%2,%3}, {%4,%5,%6,%7}, {%8,%9}, {%0,%1,%2,%3};"
        : "+f"(acc[0]), "+f"(acc[1]), "+f"(acc[2]), "+f"(acc[3])
        : "r"(a[0]), "r"(a[1]), "r"(a[2]), "r"(a[3]), "r"(b[0]), "r"(b[1]));
}

__global__ __launch_bounds__(256) void mma_f16x3_nt(
    const float* __restrict__ A, const float* __restrict__ B, float* __restrict__ C,
    int M, int Nout, int K)
{
    __shared__ uint32_t AsH[2][8 * SMS];
    __shared__ uint32_t AsL[2][8 * SMS];
    __shared__ uint32_t BsH[2][8 * SMS];
    __shared__ uint32_t BsL[2][8 * SMS];

    int bm = blockIdx.x, bn = blockIdx.y;
    int tid = threadIdx.x;
    int lane = tid & 31;
    int warp = tid >> 5;
    int wm = warp >> 2;
    int wn = warp & 3;
    int mb = wm * 64;
    int nb = wn * 32;
    int qk = lane & 3;
    int qm = lane >> 2;

    int lrow = tid >> 1;
    int lk2  = (tid & 1) * 4;
    int aRow = bm * 128 + lrow;
    int bRow = bn * 128 + lrow;
    bool aOk = aRow < M;
    bool bOk = bRow < Nout;
    const float* apBase = A + (size_t)aRow * K + lk2 * 2;
    const float* bpBase = B + (size_t)bRow * K + lk2 * 2;

    float acc[4][4][4];
    #pragma unroll
    for (int i = 0; i < 4; i++)
        #pragma unroll
        for (int j = 0; j < 4; j++)
            #pragma unroll
            for (int c = 0; c < 4; c++) acc[i][j][c] = 0.f;

    float a[8] = {0,0,0,0,0,0,0,0};
    float b[8] = {0,0,0,0,0,0,0,0};
    if (aOk) {
        float4 v0 = *(const float4*)apBase;
        float4 v1 = *(const float4*)(apBase + 4);
        a[0]=v0.x; a[1]=v0.y; a[2]=v0.z; a[3]=v0.w;
        a[4]=v1.x; a[5]=v1.y; a[6]=v1.z; a[7]=v1.w;
    }
    if (bOk) {
        float4 v0 = *(const float4*)bpBase;
        float4 v1 = *(const float4*)(bpBase + 4);
        b[0]=v0.x; b[1]=v0.y; b[2]=v0.z; b[3]=v0.w;
        b[4]=v1.x; b[5]=v1.y; b[6]=v1.z; b[7]=v1.w;
    }
    #pragma unroll
    for (int q = 0; q < 4; q++) {
        uint32_t hi, lo;
        split_h2(a[2*q], a[2*q+1], hi, lo);
        AsH[0][(lk2 + q) * SMS + lrow] = hi;
        AsL[0][(lk2 + q) * SMS + lrow] = lo;
        split_h2(b[2*q], b[2*q+1], hi, lo);
        BsH[0][(lk2 + q) * SMS + lrow] = hi;
        BsL[0][(lk2 + q) * SMS + lrow] = lo;
    }

    int nChunks = K >> 4;
    for (int c = 0; c < nChunks; c++) {
        int cur = c & 1;
        __syncthreads();

        if (c + 1 < nChunks) {
            if (aOk) {
                const float* ap = apBase + (c + 1) * 16;
                float4 v0 = *(const float4*)ap;
                float4 v1 = *(const float4*)(ap + 4);
                a[0]=v0.x; a[1]=v0.y; a[2]=v0.z; a[3]=v0.w;
                a[4]=v1.x; a[5]=v1.y; a[6]=v1.z; a[7]=v1.w;
            }
            if (bOk) {
                const float* bp = bpBase + (c + 1) * 16;
                float4 v0 = *(const float4*)bp;
                float4 v1 = *(const float4*)(bp + 4);
                b[0]=v0.x; b[1]=v0.y; b[2]=v0.z; b[3]=v0.w;
                b[4]=v1.x; b[5]=v1.y; b[6]=v1.z; b[7]=v1.w;
            }
        }

        uint32_t afH[4][4], afL[4][4];
        #pragma unroll
        for (int i = 0; i < 4; i++) {
            int mrow = mb + i * 16 + qm;
            int o0 = qk * SMS + mrow;
            int o1 = (qk + 4) * SMS + mrow;
            afH[i][0] = AsH[cur][o0];     afL[i][0] = AsL[cur][o0];
            afH[i][1] = AsH[cur][o0 + 8]; afL[i][1] = AsL[cur][o0 + 8];
            afH[i][2] = AsH[cur][o1];     afL[i][2] = AsL[cur][o1];
            afH[i][3] = AsH[cur][o1 + 8]; afL[i][3] = AsL[cur][o1 + 8];
        }
        uint32_t bfH[4][2], bfL[4][2];
        #pragma unroll
        for (int j = 0; j < 4; j++) {
            int ncol = nb + j * 8 + qm;
            bfH[j][0] = BsH[cur][qk * SMS + ncol];
            bfH[j][1] = BsH[cur][(qk + 4) * SMS + ncol];
            bfL[j][0] = BsL[cur][qk * SMS + ncol];
            bfL[j][1] = BsL[cur][(qk + 4) * SMS + ncol];
        }
        #pragma unroll
        for (int i = 0; i < 4; i++)
            #pragma unroll
            for (int j = 0; j < 4; j++) {
                mma_f16(acc[i][j], afL[i], bfH[j]);
                mma_f16(acc[i][j], afH[i], bfL[j]);
                mma_f16(acc[i][j], afH[i], bfH[j]);
            }

        if (c + 1 < nChunks) {
            int nxt = cur ^ 1;
            #pragma unroll
            for (int q = 0; q < 4; q++) {
                uint32_t hi, lo;
                split_h2(a[2*q], a[2*q+1], hi, lo);
                AsH[nxt][(lk2 + q) * SMS + lrow] = hi;
                AsL[nxt][(lk2 + q) * SMS + lrow] = lo;
                split_h2(b[2*q], b[2*q+1], hi, lo);
                BsH[nxt][(lk2 + q) * SMS + lrow] = hi;
                BsL[nxt][(lk2 + q) * SMS + lrow] = lo;
            }
        }
    }

    #pragma unroll
    for (int i = 0; i < 4; i++) {
        int r0 = bm * 128 + mb + i * 16 + qm;
        int r1 = r0 + 8;
        #pragma unroll
        for (int j = 0; j < 4; j++) {
            int col = bn * 128 + nb + j * 8 + (lane & 3) * 2;
            if (r0 < M)
                *(float2*)(C + (size_t)r0 * Nout + col) = make_float2(acc[i][j][0], acc[i][j][1]);
            if (r1 < M)
                *(float2*)(C + (size_t)r1 * Nout + col) = make_float2(acc[i][j][2], acc[i][j][3]);
        }
    }
}

// ---------------- fused GRU elementwise (float4) ----------------
// gi = deg*Y[0:384] + Ys + se*u1 + deg*u2 + b_ih ; gh = Y[384:768] + b_hh
__global__ void gru_kernel(const float* __restrict__ hv,
                           const float* __restrict__ b_ih, const float* __restrict__ b_hh,
                           const float* __restrict__ u1, const float* __restrict__ u2,
                           float* __restrict__ out, int N)
{
    int idx = blockIdx.x * blockDim.x + threadIdx.x;   // N*32 threads
    if (idx >= N * 32) return;
    int n = idx >> 5, q = idx & 31;                    // q: float4 slot over 128 channels
    float d = g_deg[n], s = g_se[n];
    const float4* Y  = (const float4*)(g_Y  + (size_t)n * H6);
    const float4* Ys = (const float4*)(g_Ys + (size_t)n * H3);
    const float4* U1 = (const float4*)u1;
    const float4* U2 = (const float4*)u2;
    const float4* BI = (const float4*)b_ih;
    const float4* BH = (const float4*)b_hh;

    float4 o;
    float4 hvv = ((const float4*)(hv + (size_t)n * H))[q];

    #pragma unroll
    for (int lane4 = 0; lane4 < 1; lane4++) {}  // (structure kept simple)

    // per gate g: channel block offset g*32 + q (in float4 units of 384 -> 96 slots)
    float4 yr = Y[q],        yz = Y[q + 32],      yn = Y[q + 64];
    float4 hr4 = Y[q + 96],  hz4 = Y[q + 128],    hn4 = Y[q + 160];
    float4 sr = Ys[q],       sz = Ys[q + 32],     sn = Ys[q + 64];
    float4 u1r = U1[q],      u1z = U1[q + 32],    u1n = U1[q + 64];
    float4 u2r = U2[q],      u2z = U2[q + 32],    u2n = U2[q + 64];
    float4 bir = BI[q],      biz = BI[q + 32],    bin_ = BI[q + 64];
    float4 bhr = BH[q],      bhz = BH[q + 32],    bhn = BH[q + 64];

    #pragma unroll
    for (int c = 0; c < 4; c++) {
        float ir = d * ((&yr.x)[c]) + (&sr.x)[c] + s * (&u1r.x)[c] + d * (&u2r.x)[c] + (&bir.x)[c];
        float iz = d * ((&yz.x)[c]) + (&sz.x)[c] + s * (&u1z.x)[c] + d * (&u2z.x)[c] + (&biz.x)[c];
        float in_ = d * ((&yn.x)[c]) + (&sn.x)[c] + s * (&u1n.x)[c] + d * (&u2n.x)[c] + (&bin_.x)[c];
        float hr = (&hr4.x)[c] + (&bhr.x)[c];
        float hz = (&hz4.x)[c] + (&bhz.x)[c];
        float hn = (&hn4.x)[c] + (&bhn.x)[c];
        float r = 1.f / (1.f + expf(-(ir + hr)));
        float z = 1.f / (1.f + expf(-(iz + hz)));
        float nn = tanhf(in_ + r * hn);
        (&o.x)[c] = (1.f - z) * nn + z * (&hvv.x)[c];
    }
    ((float4*)(out + (size_t)n * H))[q] = o;
}

// ---------------- launch ----------------
extern "C" void kernel_launch(void* const* d_in, const int* in_sizes, int n_in,
                              void* d_out, int out_size)
{
    const float* hv0   = (const float*)d_in[0];
    const float* he    = (const float*)d_in[1];
    const int*   src   = (const int*)d_in[2];
    const int*   dst   = (const int*)d_in[3];
    const float* W_msg = (const float*)d_in[4];
    const float* b_msg = (const float*)d_in[5];
    const float* W_ih  = (const float*)d_in[6];
    const float* W_hh  = (const float*)d_in[7];
    const float* b_ih  = (const float*)d_in[8];
    const float* b_hh  = (const float*)d_in[9];

    int N = in_sizes[0] / H;
    int E = in_sizes[2];
    int T = in_sizes[8] / H3;
    if (T > MAXT) T = MAXT;

    static cudaStream_t s2 = nullptr;
    static cudaEvent_t evStart = nullptr, evFold = nullptr, evPrep = nullptr,
                       evS2 = nullptr, evGru = nullptr;
    if (!s2) {
        cudaStreamCreateWithFlags(&s2, cudaStreamNonBlocking);
        cudaEventCreateWithFlags(&evStart, cudaEventDisableTiming);
        cudaEventCreateWithFlags(&evFold,  cudaEventDisableTiming);
        cudaEventCreateWithFlags(&evPrep,  cudaEventDisableTiming);
        cudaEventCreateWithFlags(&evS2,    cudaEventDisableTiming);
        cudaEventCreateWithFlags(&evGru,   cudaEventDisableTiming);
    }

    float *pS, *pY, *pYs, *ph0, *ph1, *pdeg, *pse, *pWbig, *pWcs, *pu1, *pu2;
    cudaGetSymbolAddress((void**)&pS,   g_S);
    cudaGetSymbolAddress((void**)&pY,   g_Y);
    cudaGetSymbolAddress((void**)&pYs,  g_Ys);
    cudaGetSymbolAddress((void**)&ph0,  g_h0);
    cudaGetSymbolAddress((void**)&ph1,  g_h1);
    cudaGetSymbolAddress((void**)&pdeg, g_deg);
    cudaGetSymbolAddress((void**)&pse,  g_se);
    cudaGetSymbolAddress((void**)&pWbig, g_Wbig);
    cudaGetSymbolAddress((void**)&pWcs,  g_Wcs);
    cudaGetSymbolAddress((void**)&pu1,   g_u1);
    cudaGetSymbolAddress((void**)&pu2,   g_u2);

    int nb = (N + 1023) / 1024;

    // fork: s2 = weight folds; main = CSR build
    cudaEventRecord(evStart, 0);
    cudaStreamWaitEvent(s2, evStart, 0);

    long wc_total = (long)T * H3 * H2;
    fold_wc_kernel<<<(int)((wc_total + 255) / 256), 256, 0, s2>>>(W_ih, W_msg, T);
    copy_whh_kernel<<<(T * H3 * H / 4 + 255) / 256, 256, 0, s2>>>(W_hh, T);
    fold_u_kernel<<<(T * H3 + 255) / 256, 256, 0, s2>>>(W_ih, W_msg, b_msg, T);
    cudaEventRecord(evFold, s2);

    zero2_kernel<<<128, 256>>>(pdeg, pse, N);
    degse_kernel<<<(E + 255) / 256, 256>>>(dst, he, E);
    scan1_kernel<<<nb, 1024>>>(N);
    scan2_kernel<<<1, 32>>>(nb);
    scan3_kernel<<<nb, 1024>>>(N, E);
    fill_kernel<<<(E + 255) / 256, 256>>>(src, dst, E);
    cudaEventRecord(evPrep, 0);
    cudaStreamWaitEvent(s2, evPrep, 0);   // s2 rounds need CSR
    cudaStreamWaitEvent(0, evFold, 0);    // main GEMMs need folds

    const float* cur = hv0;
    dim3 gY((N + 127) / 128, H6 / 128);   // Y GEMM: Nout=768
    dim3 gS((N + 127) / 128, H3 / 128);   // Ys GEMM: Nout=384
    for (int t = 0; t < T; t++) {
        // main: Y = hv @ [Wc_d ; W_hh]^T   (independent of gather)
        mma_f16x3_nt<<<gY, 256>>>(cur, pWbig + (size_t)t * H6 * H, pY, N, H6, H);

        // s2: gather S -> Ys = S @ Wc_s^T
        if (t > 0) cudaStreamWaitEvent(s2, evGru, 0);
        gatherx_kernel<<<(N * 32 + 255) / 256, 256, 0, s2>>>(cur, N);
        mma_f16x3_nt<<<gS, 256, 0, s2>>>(pS, pWcs + (size_t)t * H3 * H, pYs, N, H3, H);
        cudaEventRecord(evS2, s2);

        // join -> GRU on main
        cudaStreamWaitEvent(0, evS2, 0);
        float* outp = (t == T - 1) ? (float*)d_out : ((t & 1) ? ph1 : ph0);
        gru_kernel<<<(N * 32 + 255) / 256, 256>>>(cur, b_ih + (size_t)t * H3, b_hh + (size_t)t * H3,
                                                  pu1 + (size_t)t * H3, pu2 + (size_t)t * H3,
                                                  outp, N);
        cudaEventRecord(evGru, 0);
        cur = outp;
    }
}

// round 9
// speedup vs baseline: 1.1809x; 1.1809x over previous
#include <cuda_runtime.h>
#include <cuda_fp16.h>
#include <math.h>
#include <stdint.h>

#define H   128
#define H2  256
#define H3  384
#define WMC 257          // W_msg columns = 2H+1

#define MAXN 50000
#define MAXE 800000
#define MAXT 4
#define MAXNB ((MAXN + 1023) / 1024)

// ---------------- scratch (static device globals; no allocation) ----------------
__device__ float g_S  [(size_t)MAXN * H];    // gathered sum of hv[src] into dst
__device__ float g_gi [(size_t)MAXN * H3];
__device__ float g_gh [(size_t)MAXN * H3];
__device__ float g_h0 [(size_t)MAXN * H];
__device__ float g_h1 [(size_t)MAXN * H];
__device__ float g_deg[MAXN];
__device__ float g_se [MAXN];
__device__ float g_Wc [(size_t)MAXT * H3 * H2];  // W_ih @ W_msg[:, :2H]  (K=256 layout)
__device__ float g_u1 [MAXT * H3];               // W_ih @ w_e
__device__ float g_u2 [MAXT * H3];               // W_ih @ b_msg
__device__ int   g_off [MAXN + 1];               // CSR offsets (by dst)
__device__ int   g_cur [MAXN];                   // fill cursors
__device__ int   g_csrc[MAXE];                   // CSR src lists
__device__ int   g_bsum[MAXNB];                  // scan partials
__device__ int   g_bpre[MAXNB];

// ---------------- utility ----------------
__global__ void zero2_kernel(float* __restrict__ p, float* __restrict__ q, int n) {
    int i = blockIdx.x * blockDim.x + threadIdx.x;
    int stride = gridDim.x * blockDim.x;
    for (int k = i; k < n; k += stride) { p[k] = 0.f; q[k] = 0.f; }
}

__global__ void degse_kernel(const int* __restrict__ dst, const float* __restrict__ he, int E) {
    int e = blockIdx.x * blockDim.x + threadIdx.x;
    if (e >= E) return;
    int d = dst[e];
    atomicAdd(&g_deg[d], 1.0f);
    atomicAdd(&g_se[d], he[e]);
}

// ---------------- CSR prefix scan: multi-block ----------------
__global__ void scan1_kernel(int N) {
    __shared__ int wsum[32];
    int i = blockIdx.x * 1024 + threadIdx.x;
    int lane = threadIdx.x & 31, wid = threadIdx.x >> 5;
    int v = (i < N) ? (int)g_deg[i] : 0;
    int x = v;
    #pragma unroll
    for (int o = 1; o < 32; o <<= 1) {
        int t = __shfl_up_sync(0xFFFFFFFFu, x, o);
        if (lane >= o) x += t;
    }
    if (lane == 31) wsum[wid] = x;
    __syncthreads();
    if (wid == 0) {
        int s = wsum[lane];
        #pragma unroll
        for (int o = 1; o < 32; o <<= 1) {
            int t = __shfl_up_sync(0xFFFFFFFFu, s, o);
            if (lane >= o) s += t;
        }
        wsum[lane] = s;
    }
    __syncthreads();
    int wpre = (wid == 0) ? 0 : wsum[wid - 1];
    if (i < N) g_off[i] = wpre + x - v;
    if (threadIdx.x == 1023) g_bsum[blockIdx.x] = wpre + x;
}

__global__ void scan2_kernel(int nb) {
    if (threadIdx.x == 0) {
        int s = 0;
        for (int b = 0; b < nb; b++) { int t = g_bsum[b]; g_bpre[b] = s; s += t; }
    }
}

__global__ void scan3_kernel(int N, int E) {
    int i = blockIdx.x * 1024 + threadIdx.x;
    if (i < N) {
        int o = g_off[i] + g_bpre[blockIdx.x];
        g_off[i] = o;
        g_cur[i] = o;
    }
    if (i == 0) g_off[N] = E;
}

__global__ void fill_kernel(const int* __restrict__ src, const int* __restrict__ dst, int E) {
    int e = blockIdx.x * blockDim.x + threadIdx.x;
    if (e >= E) return;
    int pos = atomicAdd(&g_cur[dst[e]], 1);
    g_csrc[pos] = src[e];
}

// ---------------- weight folding ----------------
__global__ void fold_wc_kernel(const float* __restrict__ W_ih, const float* __restrict__ W_msg, int T) {
    long idx = (long)blockIdx.x * blockDim.x + threadIdx.x;
    if (idx >= (long)T * H3 * H2) return;
    int k = (int)(idx % H2);
    int j = (int)((idx / H2) % H3);
    int t = (int)(idx / ((long)H2 * H3));
    const float* wi = W_ih + ((size_t)t * H3 + j) * H2;
    const float* wm = W_msg + (size_t)t * H2 * WMC + k;
    float a0 = 0.f, a1 = 0.f, a2 = 0.f, a3 = 0.f;
    #pragma unroll 2
    for (int i = 0; i < H2; i += 4) {
        a0 += __ldg(wi + i)     * __ldg(wm + (size_t)(i)     * WMC);
        a1 += __ldg(wi + i + 1) * __ldg(wm + (size_t)(i + 1) * WMC);
        a2 += __ldg(wi + i + 2) * __ldg(wm + (size_t)(i + 2) * WMC);
        a3 += __ldg(wi + i + 3) * __ldg(wm + (size_t)(i + 3) * WMC);
    }
    g_Wc[idx] = (a0 + a1) + (a2 + a3);
}

__global__ void fold_u_kernel(const float* __restrict__ W_ih, const float* __restrict__ W_msg,
                              const float* __restrict__ b_msg, int T) {
    int idx = blockIdx.x * blockDim.x + threadIdx.x;
    if (idx >= T * H3) return;
    int j = idx % H3, t = idx / H3;
    const float* wi = W_ih + ((size_t)t * H3 + j) * H2;
    const float* wm = W_msg + (size_t)t * H2 * WMC;
    const float* bm = b_msg + (size_t)t * H2;
    float a1 = 0.f, a2 = 0.f;
    for (int i = 0; i < H2; i++) {
        float w = wi[i];
        a1 += w * wm[(size_t)i * WMC + H2];
        a2 += w * bm[i];
    }
    g_u1[idx] = a1;
    g_u2[idx] = a2;
}

// ---------------- gather: S[n] = sum_{e in CSR[n]} hv[csrc[e]], one warp/node ----
__global__ void gather_kernel(const float* __restrict__ hv, int N) {
    int n = (blockIdx.x * blockDim.x + threadIdx.x) >> 5;
    int lane = threadIdx.x & 31;
    if (n >= N) return;
    int beg = g_off[n], end = g_off[n + 1];
    float4 acc0 = make_float4(0.f, 0.f, 0.f, 0.f);
    float4 acc1 = make_float4(0.f, 0.f, 0.f, 0.f);
    int e = beg;
    for (; e + 2 <= end; e += 2) {
        int s0 = __ldg(g_csrc + e);
        int s1 = __ldg(g_csrc + e + 1);
        float4 v0 = *(((const float4*)(hv + (size_t)s0 * H)) + lane);
        float4 v1 = *(((const float4*)(hv + (size_t)s1 * H)) + lane);
        acc0.x += v0.x; acc0.y += v0.y; acc0.z += v0.z; acc0.w += v0.w;
        acc1.x += v1.x; acc1.y += v1.y; acc1.z += v1.z; acc1.w += v1.w;
    }
    if (e < end) {
        int s0 = __ldg(g_csrc + e);
        float4 v0 = *(((const float4*)(hv + (size_t)s0 * H)) + lane);
        acc0.x += v0.x; acc0.y += v0.y; acc0.z += v0.z; acc0.w += v0.w;
    }
    acc0.x += acc1.x; acc0.y += acc1.y; acc0.z += acc1.z; acc0.w += acc1.w;
    ((float4*)(g_S + (size_t)n * H))[lane] = acc0;
}

// ---------------- 3xFP16 tensor-core GEMM (NT): C = A @ B^T, fp32-accurate ---------
// template<GI>: if GI, logical A[M,256] = [deg*hv | S] assembled on the fly
// (A = hv, A2 = S, deg per-row); else plain A[M,K].
#define SMS 136

__device__ __forceinline__ void split_h2(float x, float y, uint32_t& hi, uint32_t& lo) {
    __half hx = __float2half_rn(x);
    __half hy = __float2half_rn(y);
    __half lx = __float2half_rn(x - __half2float(hx));
    __half ly = __float2half_rn(y - __half2float(hy));
    __half2 h = __halves2half2(hx, hy);
    __half2 l = __halves2half2(lx, ly);
    hi = *(uint32_t*)&h;
    lo = *(uint32_t*)&l;
}

__device__ __forceinline__ void mma_f16(float* acc, const uint32_t* a, const uint32_t* b) {
    asm volatile(
        "mma.sync.aligned.m16n8k16.row.col.f32.f16.f16.f32 "
        "{%0,%1,%2,%3}, {%4,%5,%6,%7}, {%8,%9}, {%0,%1,%2,%3};"
        : "+f"(acc[0]), "+f"(acc[1]), "+f"(acc[2]), "+f"(acc[3])
        : "r"(a[0]), "r"(a[1]), "r"(a[2]), "r"(a[3]), "r"(b[0]), "r"(b[1]));
}

template<bool GI>
__global__ __launch_bounds__(256) void mma_f16x3_k(
    const float* __restrict__ A, const float* __restrict__ A2,
    const float* __restrict__ degp,
    const float* __restrict__ B, float* __restrict__ C,
    int M, int Nout, int K)
{
    __shared__ uint32_t AsH[2][8 * SMS];
    __shared__ uint32_t AsL[2][8 * SMS];
    __shared__ uint32_t BsH[2][8 * SMS];
    __shared__ uint32_t BsL[2][8 * SMS];

    int bm = blockIdx.x, bn = blockIdx.y;
    int tid = threadIdx.x;
    int lane = tid & 31;
    int warp = tid >> 5;
    int wm = warp >> 2;
    int wn = warp & 3;
    int mb = wm * 64;
    int nb = wn * 32;
    int qk = lane & 3;
    int qm = lane >> 2;

    int lrow = tid >> 1;
    int lk2  = (tid & 1) * 4;        // half2-slot base (k offset = lk2*2)
    int aRow = bm * 128 + lrow;
    int bRow = bn * 128 + lrow;
    bool aOk = aRow < M;
    bool bOk = bRow < Nout;
    const float* apRow  = GI ? (A  + (size_t)aRow * H) : (A + (size_t)aRow * K);
    const float* ap2Row = GI ? (A2 + (size_t)aRow * H) : nullptr;
    const float* bpBase = B + (size_t)bRow * K + lk2 * 2;
    float dg = (GI && aOk) ? degp[aRow] : 1.f;

    float acc[4][4][4];
    #pragma unroll
    for (int i = 0; i < 4; i++)
        #pragma unroll
        for (int j = 0; j < 4; j++)
            #pragma unroll
            for (int c = 0; c < 4; c++) acc[i][j][c] = 0.f;

    float a[8] = {0,0,0,0,0,0,0,0};
    float b[8] = {0,0,0,0,0,0,0,0};

    // ---- load chunk 0 ----
    if (aOk) {
        const float* ap;
        float sc;
        if (GI) { ap = apRow + lk2 * 2; sc = dg; }       // chunk 0 < 8 -> deg*hv
        else    { ap = apRow + lk2 * 2; sc = 1.f; }
        float4 v0 = *(const float4*)ap;
        float4 v1 = *(const float4*)(ap + 4);
        a[0]=v0.x*sc; a[1]=v0.y*sc; a[2]=v0.z*sc; a[3]=v0.w*sc;
        a[4]=v1.x*sc; a[5]=v1.y*sc; a[6]=v1.z*sc; a[7]=v1.w*sc;
    }
    if (bOk) {
        float4 v0 = *(const float4*)bpBase;
        float4 v1 = *(const float4*)(bpBase + 4);
        b[0]=v0.x; b[1]=v0.y; b[2]=v0.z; b[3]=v0.w;
        b[4]=v1.x; b[5]=v1.y; b[6]=v1.z; b[7]=v1.w;
    }
    #pragma unroll
    for (int q = 0; q < 4; q++) {
        uint32_t hi, lo;
        split_h2(a[2*q], a[2*q+1], hi, lo);
        AsH[0][(lk2 + q) * SMS + lrow] = hi;
        AsL[0][(lk2 + q) * SMS + lrow] = lo;
        split_h2(b[2*q], b[2*q+1], hi, lo);
        BsH[0][(lk2 + q) * SMS + lrow] = hi;
        BsL[0][(lk2 + q) * SMS + lrow] = lo;
    }

    int nChunks = K >> 4;
    for (int c = 0; c < nChunks; c++) {
        int cur = c & 1;
        __syncthreads();

        // prefetch next chunk
        if (c + 1 < nChunks) {
            int cn = c + 1;
            if (aOk) {
                const float* ap;
                float sc;
                if (GI) {
                    if (cn < 8) { ap = apRow  + cn * 16 + lk2 * 2;        sc = dg;  }
                    else        { ap = ap2Row + (cn - 8) * 16 + lk2 * 2;  sc = 1.f; }
                } else {
                    ap = apRow + cn * 16 + lk2 * 2; sc = 1.f;
                }
                float4 v0 = *(const float4*)ap;
                float4 v1 = *(const float4*)(ap + 4);
                a[0]=v0.x*sc; a[1]=v0.y*sc; a[2]=v0.z*sc; a[3]=v0.w*sc;
                a[4]=v1.x*sc; a[5]=v1.y*sc; a[6]=v1.z*sc; a[7]=v1.w*sc;
            }
            if (bOk) {
                const float* bp = bpBase + cn * 16;
                float4 v0 = *(const float4*)bp;
                float4 v1 = *(const float4*)(bp + 4);
                b[0]=v0.x; b[1]=v0.y; b[2]=v0.z; b[3]=v0.w;
                b[4]=v1.x; b[5]=v1.y; b[6]=v1.z; b[7]=v1.w;
            }
        }

        uint32_t afH[4][4], afL[4][4];
        #pragma unroll
        for (int i = 0; i < 4; i++) {
            int mrow = mb + i * 16 + qm;
            int o0 = qk * SMS + mrow;
            int o1 = (qk + 4) * SMS + mrow;
            afH[i][0] = AsH[cur][o0];     afL[i][0] = AsL[cur][o0];
            afH[i][1] = AsH[cur][o0 + 8]; afL[i][1] = AsL[cur][o0 + 8];
            afH[i][2] = AsH[cur][o1];     afL[i][2] = AsL[cur][o1];
            afH[i][3] = AsH[cur][o1 + 8]; afL[i][3] = AsL[cur][o1 + 8];
        }
        uint32_t bfH[4][2], bfL[4][2];
        #pragma unroll
        for (int j = 0; j < 4; j++) {
            int ncol = nb + j * 8 + qm;
            bfH[j][0] = BsH[cur][qk * SMS + ncol];
            bfH[j][1] = BsH[cur][(qk + 4) * SMS + ncol];
            bfL[j][0] = BsL[cur][qk * SMS + ncol];
            bfL[j][1] = BsL[cur][(qk + 4) * SMS + ncol];
        }
        #pragma unroll
        for (int i = 0; i < 4; i++)
            #pragma unroll
            for (int j = 0; j < 4; j++) {
                mma_f16(acc[i][j], afL[i], bfH[j]);
                mma_f16(acc[i][j], afH[i], bfL[j]);
                mma_f16(acc[i][j], afH[i], bfH[j]);
            }

        if (c + 1 < nChunks) {
            int nxt = cur ^ 1;
            #pragma unroll
            for (int q = 0; q < 4; q++) {
                uint32_t hi, lo;
                split_h2(a[2*q], a[2*q+1], hi, lo);
                AsH[nxt][(lk2 + q) * SMS + lrow] = hi;
                AsL[nxt][(lk2 + q) * SMS + lrow] = lo;
                split_h2(b[2*q], b[2*q+1], hi, lo);
                BsH[nxt][(lk2 + q) * SMS + lrow] = hi;
                BsL[nxt][(lk2 + q) * SMS + lrow] = lo;
            }
        }
    }

    #pragma unroll
    for (int i = 0; i < 4; i++) {
        int r0 = bm * 128 + mb + i * 16 + qm;
        int r1 = r0 + 8;
        #pragma unroll
        for (int j = 0; j < 4; j++) {
            int col = bn * 128 + nb + j * 8 + (lane & 3) * 2;
            if (r0 < M)
                *(float2*)(C + (size_t)r0 * Nout + col) = make_float2(acc[i][j][0], acc[i][j][1]);
            if (r1 < M)
                *(float2*)(C + (size_t)r1 * Nout + col) = make_float2(acc[i][j][2], acc[i][j][3]);
        }
    }
}

// ---------------- fused GRU elementwise (float4) ----------------
__global__ void gru_kernel(const float* __restrict__ hv,
                           const float* __restrict__ b_ih, const float* __restrict__ b_hh,
                           const float* __restrict__ u1, const float* __restrict__ u2,
                           float* __restrict__ out, int N)
{
    int idx = blockIdx.x * blockDim.x + threadIdx.x;   // N*32 threads
    if (idx >= N * 32) return;
    int n = idx >> 5, q = idx & 31;                    // q: float4 slot over 128 channels
    float d = g_deg[n], s = g_se[n];
    const float4* GI4 = (const float4*)(g_gi + (size_t)n * H3);
    const float4* GH4 = (const float4*)(g_gh + (size_t)n * H3);
    const float4* U1 = (const float4*)u1;
    const float4* U2 = (const float4*)u2;
    const float4* BI = (const float4*)b_ih;
    const float4* BH = (const float4*)b_hh;

    float4 hvv = ((const float4*)(hv + (size_t)n * H))[q];
    float4 ir4 = GI4[q], iz4 = GI4[q + 32], in4 = GI4[q + 64];
    float4 hr4 = GH4[q], hz4 = GH4[q + 32], hn4 = GH4[q + 64];
    float4 u1r = U1[q],  u1z = U1[q + 32],  u1n = U1[q + 64];
    float4 u2r = U2[q],  u2z = U2[q + 32],  u2n = U2[q + 64];
    float4 bir = BI[q],  biz = BI[q + 32],  bin_ = BI[q + 64];
    float4 bhr = BH[q],  bhz = BH[q + 32],  bhn = BH[q + 64];

    float4 o;
    #pragma unroll
    for (int c = 0; c < 4; c++) {
        float ir = (&ir4.x)[c] + s * (&u1r.x)[c] + d * (&u2r.x)[c] + (&bir.x)[c];
        float iz = (&iz4.x)[c] + s * (&u1z.x)[c] + d * (&u2z.x)[c] + (&biz.x)[c];
        float in_ = (&in4.x)[c] + s * (&u1n.x)[c] + d * (&u2n.x)[c] + (&bin_.x)[c];
        float hr = (&hr4.x)[c] + (&bhr.x)[c];
        float hz = (&hz4.x)[c] + (&bhz.x)[c];
        float hn = (&hn4.x)[c] + (&bhn.x)[c];
        float r = 1.f / (1.f + expf(-(ir + hr)));
        float z = 1.f / (1.f + expf(-(iz + hz)));
        float nn = tanhf(in_ + r * hn);
        (&o.x)[c] = (1.f - z) * nn + z * (&hvv.x)[c];
    }
    ((float4*)(out + (size_t)n * H))[q] = o;
}

// ---------------- launch ----------------
extern "C" void kernel_launch(void* const* d_in, const int* in_sizes, int n_in,
                              void* d_out, int out_size)
{
    const float* hv0   = (const float*)d_in[0];
    const float* he    = (const float*)d_in[1];
    const int*   src   = (const int*)d_in[2];
    const int*   dst   = (const int*)d_in[3];
    const float* W_msg = (const float*)d_in[4];
    const float* b_msg = (const float*)d_in[5];
    const float* W_ih  = (const float*)d_in[6];
    const float* W_hh  = (const float*)d_in[7];
    const float* b_ih  = (const float*)d_in[8];
    const float* b_hh  = (const float*)d_in[9];

    int N = in_sizes[0] / H;
    int E = in_sizes[2];
    int T = in_sizes[8] / H3;
    if (T > MAXT) T = MAXT;

    static cudaStream_t s2 = nullptr;
    static cudaEvent_t evStart = nullptr, evFold = nullptr, evGh = nullptr, evGru = nullptr;
    if (!s2) {
        cudaStreamCreateWithFlags(&s2, cudaStreamNonBlocking);
        cudaEventCreateWithFlags(&evStart, cudaEventDisableTiming);
        cudaEventCreateWithFlags(&evFold,  cudaEventDisableTiming);
        cudaEventCreateWithFlags(&evGh,    cudaEventDisableTiming);
        cudaEventCreateWithFlags(&evGru,   cudaEventDisableTiming);
    }

    float *pS, *pgi, *pgh, *ph0, *ph1, *pdeg, *pse, *pWc, *pu1, *pu2;
    cudaGetSymbolAddress((void**)&pS,   g_S);
    cudaGetSymbolAddress((void**)&pgi,  g_gi);
    cudaGetSymbolAddress((void**)&pgh,  g_gh);
    cudaGetSymbolAddress((void**)&ph0,  g_h0);
    cudaGetSymbolAddress((void**)&ph1,  g_h1);
    cudaGetSymbolAddress((void**)&pdeg, g_deg);
    cudaGetSymbolAddress((void**)&pse,  g_se);
    cudaGetSymbolAddress((void**)&pWc,  g_Wc);
    cudaGetSymbolAddress((void**)&pu1,  g_u1);
    cudaGetSymbolAddress((void**)&pu2,  g_u2);

    int nb = (N + 1023) / 1024;

    // fork: s2 = weight folds; main = CSR build
    cudaEventRecord(evStart, 0);
    cudaStreamWaitEvent(s2, evStart, 0);

    long wc_total = (long)T * H3 * H2;
    fold_wc_kernel<<<(int)((wc_total + 255) / 256), 256, 0, s2>>>(W_ih, W_msg, T);
    fold_u_kernel<<<(T * H3 + 255) / 256, 256, 0, s2>>>(W_ih, W_msg, b_msg, T);
    cudaEventRecord(evFold, s2);

    zero2_kernel<<<128, 256>>>(pdeg, pse, N);
    degse_kernel<<<(E + 255) / 256, 256>>>(dst, he, E);
    scan1_kernel<<<nb, 1024>>>(N);
    scan2_kernel<<<1, 32>>>(nb);
    scan3_kernel<<<nb, 1024>>>(N, E);
    fill_kernel<<<(E + 255) / 256, 256>>>(src, dst, E);

    const float* cur = hv0;
    dim3 g1((N + 127) / 128, 3);
    for (int t = 0; t < T; t++) {
        // main: gather -> gi GEMM ([deg*hv | S] @ Wc^T, K=256)
        gather_kernel<<<(N * 32 + 255) / 256, 256>>>(cur, N);
        if (t == 0) cudaStreamWaitEvent(0, evFold, 0);
        mma_f16x3_k<true><<<g1, 256>>>(cur, pS, pdeg,
                                       pWc + (size_t)t * H3 * H2, pgi, N, H3, H2);

        // s2: gh GEMM (plain, K=128; independent of gather)
        if (t > 0) cudaStreamWaitEvent(s2, evGru, 0);
        mma_f16x3_k<false><<<g1, 256, 0, s2>>>(cur, nullptr, nullptr,
                                               W_hh + (size_t)t * H3 * H, pgh, N, H3, H);
        cudaEventRecord(evGh, s2);

        // join -> GRU on main
        cudaStreamWaitEvent(0, evGh, 0);
        float* outp = (t == T - 1) ? (float*)d_out : ((t & 1) ? ph1 : ph0);
        gru_kernel<<<(N * 32 + 255) / 256, 256>>>(cur, b_ih + (size_t)t * H3, b_hh + (size_t)t * H3,
                                                  pu1 + (size_t)t * H3, pu2 + (size_t)t * H3,
                                                  outp, N);
        cudaEventRecord(evGru, 0);
        cur = outp;
    }
}